// round 6
// baseline (speedup 1.0000x reference)
#include <cuda_runtime.h>
#include <math.h>

#define N_NODES 25000
#define N_EDGES 250000
#define DIM 64
#define HEADS 4
#define C 256            // HEADS*DIM
#define EB 8             // edges per tile

// Scratch
__device__ float g_P[N_NODES * C];                       // x @ W_top (25.6 MB, L2-resident)
__device__ __align__(16) float g_num[N_NODES * C];       // unnormalized aggregation
__device__ float g_denom[N_NODES * HEADS];

__device__ __forceinline__ float sp(float x) {
    return fmaxf(x, 0.f) + __logf(1.f + __expf(-fabsf(x)));
}

__device__ __forceinline__ unsigned long long pk2(float a, float b) {
    unsigned long long r;
    asm("mov.b64 %0, {%1, %2};" : "=l"(r) : "f"(a), "f"(b));
    return r;
}
__device__ __forceinline__ void ffma2(unsigned long long& acc,
                                      unsigned long long a, unsigned long long b) {
    asm("fma.rn.f32x2 %0, %1, %2, %0;" : "+l"(acc) : "l"(a), "l"(b));
}
__device__ __forceinline__ float2 unpk2(unsigned long long v) {
    float2 f;
    asm("mov.b64 {%0, %1}, %2;" : "=f"(f.x), "=f"(f.y) : "l"(v));
    return f;
}

__global__ void k_initA() {
    int i = blockIdx.x * blockDim.x + threadIdx.x;
    if (i < N_NODES * C) g_num[i] = 0.f;
}
__global__ void k_initB() {
    int i = blockIdx.x * blockDim.x + threadIdx.x;
    if (i < N_NODES * HEADS) g_denom[i] = 0.f;
}

// P[n, t] = sum_k x[n,k] * W[k, t]   (W_top = first 64 rows of W)
__global__ void __launch_bounds__(256, 2) k_P(const float* __restrict__ x,
                                              const float* __restrict__ W) {
    int t = threadIdx.x;
    unsigned long long w2[DIM / 2];
#pragma unroll
    for (int k = 0; k < DIM / 2; k++) w2[k] = pk2(W[(2 * k) * C + t], W[(2 * k + 1) * C + t]);
    __shared__ float4 sx[DIM / 4];
    for (int n = blockIdx.x; n < N_NODES; n += gridDim.x) {
        __syncthreads();
        if (t < 16) sx[t] = ((const float4*)(x + n * DIM))[t];
        __syncthreads();
        unsigned long long a0 = 0ull, a1 = 0ull, a2 = 0ull, a3 = 0ull;
#pragma unroll
        for (int k4 = 0; k4 < 16; k4 += 2) {
            float4 e0 = sx[k4], e1 = sx[k4 + 1];
            ffma2(a0, pk2(e0.x, e0.y), w2[2 * k4]);
            ffma2(a1, pk2(e0.z, e0.w), w2[2 * k4 + 1]);
            ffma2(a2, pk2(e1.x, e1.y), w2[2 * k4 + 2]);
            ffma2(a3, pk2(e1.z, e1.w), w2[2 * k4 + 3]);
        }
        float2 f0 = unpk2(a0), f1 = unpk2(a1), f2 = unpk2(a2), f3 = unpk2(a3);
        g_P[n * C + t] = ((f0.x + f0.y) + (f1.x + f1.y)) + ((f2.x + f2.y) + (f3.x + f3.y));
    }
}

// Fused edge pass
__global__ void __launch_bounds__(256, 2) k_edge(
    const float* __restrict__ edge_attr, const float* __restrict__ W,
    const float* __restrict__ att, const float* __restrict__ bn_g,
    const float* __restrict__ bn_b, const float* __restrict__ bn_m,
    const float* __restrict__ bn_v, const int* __restrict__ ei) {
    int t = threadIdx.x;
    int h = t >> 6, d = t & 63;
    int warp = t >> 5, lane = t & 31;

    unsigned long long w2[DIM / 2];
#pragma unroll
    for (int k = 0; k < DIM / 2; k++)
        w2[k] = pk2(W[(DIM + 2 * k) * C + t], W[(DIM + 2 * k + 1) * C + t]);
    const float ai = att[h * 128 + d];
    const float aj = att[h * 128 + 64 + d];

    __shared__ float4 sea[EB][DIM / 4];
    __shared__ int    sii[EB], sjj[EB];
    __shared__ float  sred[EB][8];
    __shared__ float  sbn[2][HEADS];       // scale, shift
    __shared__ __align__(16) float sc[EB][C];

    if (t < HEADS) {
        float s = bn_g[t] * rsqrtf(bn_v[t] + 1e-5f);
        sbn[0][t] = s;
        sbn[1][t] = bn_b[t] - bn_m[t] * s;
    }

    const int* idx_i = ei;
    const int* idx_j = ei + N_EDGES;

    for (int base = blockIdx.x * EB; base < N_EDGES; base += gridDim.x * EB) {
        __syncthreads();
        if (t < 128) {                       // EB*16 float4s
            int ee = t >> 4, q4 = t & 15;
            sea[ee][q4] = ((const float4*)(edge_attr + (size_t)(base + ee) * DIM))[q4];
        } else if (t < 128 + EB) {
            int ee = t - 128;
            sii[ee] = idx_i[base + ee];
            sjj[ee] = idx_j[base + ee];
        }
        __syncthreads();

        // Phase 0: prefetch all 16 gathers (independent -> MLP 16)
        float pi[EB], pj[EB];
#pragma unroll
        for (int ee = 0; ee < EB; ee++) {
            pi[ee] = __ldg(&g_P[sii[ee] * C + t]);
            pj[ee] = __ldg(&g_P[sjj[ee] * C + t]);
        }

        // Phase 1: matvec only (4 independent FMA chains, depth 8)
        float qv[EB];
#pragma unroll 1
        for (int ee = 0; ee < EB; ee++) {
            unsigned long long a0 = 0ull, a1 = 0ull, a2 = 0ull, a3 = 0ull;
#pragma unroll
            for (int k4 = 0; k4 < 16; k4 += 2) {
                float4 e0 = sea[ee][k4], e1 = sea[ee][k4 + 1];
                ffma2(a0, pk2(e0.x, e0.y), w2[2 * k4]);
                ffma2(a1, pk2(e0.z, e0.w), w2[2 * k4 + 1]);
                ffma2(a2, pk2(e1.x, e1.y), w2[2 * k4 + 2]);
                ffma2(a3, pk2(e1.z, e1.w), w2[2 * k4 + 3]);
            }
            float2 f0 = unpk2(a0), f1 = unpk2(a1), f2 = unpk2(a2), f3 = unpk2(a3);
            qv[ee] = ((f0.x + f0.y) + (f1.x + f1.y)) + ((f2.x + f2.y) + (f3.x + f3.y));
        }

        // Phase 2: softplus + logit partials, 8 independent chains (overlapped MUFU)
        float oj_r[EB], part[EB];
#pragma unroll
        for (int ee = 0; ee < EB; ee++) {
            float oi = sp(pi[ee] + qv[ee]);
            float oj = sp(pj[ee] + qv[ee]);
            oj_r[ee] = oj;
            part[ee] = oi * ai + oj * aj;
        }

        // Phase 3: 8 interleaved butterfly chains
#pragma unroll
        for (int off = 16; off; off >>= 1) {
#pragma unroll
            for (int ee = 0; ee < EB; ee++)
                part[ee] += __shfl_xor_sync(0xffffffffu, part[ee], off);
        }
        if (lane == 0) {
#pragma unroll
            for (int ee = 0; ee < EB; ee++) sred[ee][warp] = part[ee];
        }
        __syncthreads();

        // Phase 4: every thread computes BN+exp for its own head; stage weighted oj
        {
            float s0 = sbn[0][h], s1 = sbn[1][h];
#pragma unroll
            for (int ee = 0; ee < EB; ee++) {
                float a = sp(sred[ee][2 * h] + sred[ee][2 * h + 1]);
                a = sp(a * s0 + s1);
                float ex = __expf(a);        // logits bounded: no max-subtract needed
                sc[ee][t] = oj_r[ee] * ex;
            }
        }
        // denom atomics in parallel (warp 0; recompute from sred)
        if (t < EB * HEADS) {
            int ee = t >> 2, hh = t & 3;
            float a = sp(sred[ee][2 * hh] + sred[ee][2 * hh + 1]);
            a = sp(a * sbn[0][hh] + sbn[1][hh]);
            atomicAdd(&g_denom[sii[ee] * HEADS + hh], __expf(a));
        }
        __syncthreads();

        // Phase 5: vector scatter
#pragma unroll
        for (int r = 0; r < 2; r++) {
            int p = t + r * 256;             // 512 quads: 8 edges x 64 quads
            int ee = p >> 6, qd = p & 63;
            const float4 v = *(const float4*)&sc[ee][qd * 4];
            float* dst = &g_num[(size_t)sii[ee] * C + qd * 4];
            asm volatile("red.global.add.v4.f32 [%0], {%1, %2, %3, %4};"
                         :: "l"(dst), "f"(v.x), "f"(v.y), "f"(v.z), "f"(v.w)
                         : "memory");
        }
    }
}

// out[n, q4] = bias + 0.25 * sum_h num[n,h,q4] / denom[n,h]   (float4 per thread)
__global__ void k_final(const float* __restrict__ bias, float* __restrict__ out) {
    int i = blockIdx.x * blockDim.x + threadIdx.x;   // N_NODES*16 quads
    if (i >= N_NODES * 16) return;
    int n = i >> 4, q = i & 15;
    float inv[HEADS];
#pragma unroll
    for (int hh = 0; hh < HEADS; hh++) {
        float dn = g_denom[n * HEADS + hh];
        inv[hh] = (dn > 0.f) ? 0.25f / dn : 0.f;
    }
    float4 acc = make_float4(0.f, 0.f, 0.f, 0.f);
#pragma unroll
    for (int hh = 0; hh < HEADS; hh++) {
        float4 v = *(const float4*)&g_num[n * C + hh * DIM + q * 4];
        acc.x += v.x * inv[hh]; acc.y += v.y * inv[hh];
        acc.z += v.z * inv[hh]; acc.w += v.w * inv[hh];
    }
    float4 b = *(const float4*)&bias[q * 4];
    acc.x += b.x; acc.y += b.y; acc.z += b.z; acc.w += b.w;
    *(float4*)&out[n * DIM + q * 4] = acc;
}

extern "C" void kernel_launch(void* const* d_in, const int* in_sizes, int n_in,
                              void* d_out, int out_size) {
    const float* x         = (const float*)d_in[0];
    const float* edge_attr = (const float*)d_in[1];
    const float* W         = (const float*)d_in[2];
    const float* att       = (const float*)d_in[3];
    const float* bias      = (const float*)d_in[4];
    const float* bn_g      = (const float*)d_in[5];
    const float* bn_b      = (const float*)d_in[6];
    const float* bn_m      = (const float*)d_in[7];
    const float* bn_v      = (const float*)d_in[8];
    const int*   ei        = (const int*)d_in[9];
    float* out = (float*)d_out;

    k_initA<<<(N_NODES * C + 255) / 256, 256>>>();
    k_initB<<<(N_NODES * HEADS + 255) / 256, 256>>>();
    k_P<<<592, 256>>>(x, W);
    k_edge<<<1184, 256>>>(edge_attr, W, att, bn_g, bn_b, bn_m, bn_v, ei);    // position 4
    k_final<<<(N_NODES * 16 + 255) / 256, 256>>>(bias, out);
}

// round 7
// speedup vs baseline: 2.0755x; 2.0755x over previous
#include <cuda_runtime.h>
#include <math.h>

#define N_NODES 25000
#define N_EDGES 250000
#define DIM 64
#define HEADS 4
#define C 256            // HEADS*DIM
#define EB 16            // edges per tile (mma m16)

// Scratch
__device__ float g_P[N_NODES * C];                       // x @ W_top (fp32 exact)
__device__ __align__(16) float g_num[N_NODES * C];       // unnormalized aggregation
__device__ float g_denom[N_NODES * HEADS];

__device__ __forceinline__ float sp(float x) {
    return fmaxf(x, 0.f) + __logf(1.f + __expf(-fabsf(x)));
}
__device__ __forceinline__ unsigned tf32(float x) {
    float r;
    asm("cvt.rna.tf32.f32 %0, %1;" : "=f"(r) : "f"(x));
    return __float_as_uint(r);
}
__device__ __forceinline__ void mma_tf32(float* d, const unsigned* a, const unsigned* b) {
    asm("mma.sync.aligned.m16n8k8.row.col.f32.tf32.tf32.f32 "
        "{%0,%1,%2,%3}, {%4,%5,%6,%7}, {%8,%9}, {%0,%1,%2,%3};"
        : "+f"(d[0]), "+f"(d[1]), "+f"(d[2]), "+f"(d[3])
        : "r"(a[0]), "r"(a[1]), "r"(a[2]), "r"(a[3]), "r"(b[0]), "r"(b[1]));
}

__device__ __forceinline__ unsigned long long pk2(float a, float b) {
    unsigned long long r;
    asm("mov.b64 %0, {%1, %2};" : "=l"(r) : "f"(a), "f"(b));
    return r;
}
__device__ __forceinline__ void ffma2(unsigned long long& acc,
                                      unsigned long long a, unsigned long long b) {
    asm("fma.rn.f32x2 %0, %1, %2, %0;" : "+l"(acc) : "l"(a), "l"(b));
}
__device__ __forceinline__ float2 unpk2(unsigned long long v) {
    float2 f;
    asm("mov.b64 {%0, %1}, %2;" : "=f"(f.x), "=f"(f.y) : "l"(v));
    return f;
}

__global__ void k_initA() {
    int i = blockIdx.x * blockDim.x + threadIdx.x;
    if (i < N_NODES * C) g_num[i] = 0.f;
}
__global__ void k_initB() {
    int i = blockIdx.x * blockDim.x + threadIdx.x;
    if (i < N_NODES * HEADS) g_denom[i] = 0.f;
}

// P[n, t] = sum_k x[n,k] * W[k, t]  (exact fp32)
__global__ void __launch_bounds__(256, 2) k_P(const float* __restrict__ x,
                                              const float* __restrict__ W) {
    int t = threadIdx.x;
    unsigned long long w2[DIM / 2];
#pragma unroll
    for (int k = 0; k < DIM / 2; k++) w2[k] = pk2(W[(2 * k) * C + t], W[(2 * k + 1) * C + t]);
    __shared__ float4 sx[DIM / 4];
    for (int n = blockIdx.x; n < N_NODES; n += gridDim.x) {
        __syncthreads();
        if (t < 16) sx[t] = ((const float4*)(x + n * DIM))[t];
        __syncthreads();
        unsigned long long a0 = 0ull, a1 = 0ull, a2 = 0ull, a3 = 0ull;
#pragma unroll
        for (int k4 = 0; k4 < 16; k4 += 2) {
            float4 e0 = sx[k4], e1 = sx[k4 + 1];
            ffma2(a0, pk2(e0.x, e0.y), w2[2 * k4]);
            ffma2(a1, pk2(e0.z, e0.w), w2[2 * k4 + 1]);
            ffma2(a2, pk2(e1.x, e1.y), w2[2 * k4 + 2]);
            ffma2(a3, pk2(e1.z, e1.w), w2[2 * k4 + 3]);
        }
        float2 f0 = unpk2(a0), f1 = unpk2(a1), f2 = unpk2(a2), f3 = unpk2(a3);
        g_P[n * C + t] = ((f0.x + f0.y) + (f1.x + f1.y)) + ((f2.x + f2.y) + (f3.x + f3.y));
    }
}

// Fused edge pass, tensor-core matvec.
// Warp w owns output cols [w*32, w*32+32) (all in head w>>1), as 4 n-blocks of 8.
__global__ void __launch_bounds__(256, 2) k_edge(
    const float* __restrict__ edge_attr, const float* __restrict__ W,
    const float* __restrict__ att, const float* __restrict__ bn_g,
    const float* __restrict__ bn_b, const float* __restrict__ bn_m,
    const float* __restrict__ bn_v, const int* __restrict__ ei) {
    const int t = threadIdx.x;
    const int w = t >> 5, lane = t & 31;
    const int g = lane >> 2, tg = lane & 3;
    const int h = w >> 1;

    // B fragments (tf32 weights), resident for the whole kernel: [nb][ks][2]
    unsigned bf[4][8][2];
#pragma unroll
    for (int nb = 0; nb < 4; nb++) {
        const int n = w * 32 + nb * 8 + g;
#pragma unroll
        for (int ks = 0; ks < 8; ks++) {
            const int k0 = ks * 8 + tg;
            bf[nb][ks][0] = tf32(W[(DIM + k0) * C + n]);
            bf[nb][ks][1] = tf32(W[(DIM + k0 + 4) * C + n]);
        }
    }

    __shared__ float sea[EB][68];      // padded: bank(e*68+k) = (4e+k)&31 -> conflict-free
    __shared__ int   sii[EB], sjj[EB];
    __shared__ float sred[EB][8];
    __shared__ float sbn[2][HEADS];

    if (t < HEADS) {
        float s = bn_g[t] * rsqrtf(bn_v[t] + 1e-5f);
        sbn[0][t] = s;
        sbn[1][t] = bn_b[t] - bn_m[t] * s;
    }

    const int* idx_i = ei;
    const int* idx_j = ei + N_EDGES;

    for (int base = blockIdx.x * EB; base < N_EDGES; base += gridDim.x * EB) {
        __syncthreads();
        {
            const int e = t >> 4, q4 = t & 15;
            const float4 v = *(const float4*)&edge_attr[(size_t)(base + e) * DIM + q4 * 4];
            *(float4*)&sea[e][q4 * 4] = v;
            if (t < EB) sii[t] = idx_i[base + t];
            else if (t < 2 * EB) sjj[t - EB] = idx_j[base + t - EB];
        }
        __syncthreads();

        const int i0 = sii[g], i8 = sii[g + 8];
        const int j0 = sjj[g], j8 = sjj[g + 8];

        // Prefetch P gathers for this thread's (edge, col-pair) cells (16 LDG.64, MLP 16)
        float2 Pi0[4], Pi8[4], Pj0[4], Pj8[4];
#pragma unroll
        for (int nb = 0; nb < 4; nb++) {
            const int c = w * 32 + nb * 8 + tg * 2;
            Pi0[nb] = *(const float2*)&g_P[i0 * C + c];
            Pi8[nb] = *(const float2*)&g_P[i8 * C + c];
            Pj0[nb] = *(const float2*)&g_P[j0 * C + c];
            Pj8[nb] = *(const float2*)&g_P[j8 * C + c];
        }

        // MMA: q[16, 32] for this warp
        float D[4][4];
#pragma unroll
        for (int nb = 0; nb < 4; nb++)
#pragma unroll
            for (int r = 0; r < 4; r++) D[nb][r] = 0.f;
#pragma unroll
        for (int ks = 0; ks < 8; ks++) {
            unsigned a[4];
            a[0] = tf32(sea[g][ks * 8 + tg]);
            a[1] = tf32(sea[g + 8][ks * 8 + tg]);
            a[2] = tf32(sea[g][ks * 8 + tg + 4]);
            a[3] = tf32(sea[g + 8][ks * 8 + tg + 4]);
#pragma unroll
            for (int nb = 0; nb < 4; nb++)
                mma_tf32(D[nb], a, bf[nb][ks]);
        }

        // softplus + logit partials; D overwritten in-place with oj
        float part0 = 0.f, part8 = 0.f;
#pragma unroll
        for (int nb = 0; nb < 4; nb++) {
            const int c = w * 32 + nb * 8 + tg * 2;
            const int d0 = c & 63;
            const float ai0 = att[h * 128 + d0],      ai1 = att[h * 128 + d0 + 1];
            const float aj0 = att[h * 128 + 64 + d0], aj1 = att[h * 128 + 64 + d0 + 1];
            float q, oi;
            q = D[nb][0]; oi = sp(Pi0[nb].x + q); D[nb][0] = sp(Pj0[nb].x + q);
            part0 = fmaf(oi, ai0, fmaf(D[nb][0], aj0, part0));
            q = D[nb][1]; oi = sp(Pi0[nb].y + q); D[nb][1] = sp(Pj0[nb].y + q);
            part0 = fmaf(oi, ai1, fmaf(D[nb][1], aj1, part0));
            q = D[nb][2]; oi = sp(Pi8[nb].x + q); D[nb][2] = sp(Pj8[nb].x + q);
            part8 = fmaf(oi, ai0, fmaf(D[nb][2], aj0, part8));
            q = D[nb][3]; oi = sp(Pi8[nb].y + q); D[nb][3] = sp(Pj8[nb].y + q);
            part8 = fmaf(oi, ai1, fmaf(D[nb][3], aj1, part8));
        }
        // reduce across the 4 lanes sharing each edge-row
        part0 += __shfl_xor_sync(0xffffffffu, part0, 1);
        part0 += __shfl_xor_sync(0xffffffffu, part0, 2);
        part8 += __shfl_xor_sync(0xffffffffu, part8, 1);
        part8 += __shfl_xor_sync(0xffffffffu, part8, 2);
        if (tg == 0) { sred[g][w] = part0; sred[g + 8][w] = part8; }
        __syncthreads();

        // denom atomics (one thread per (edge, head))
        if (t < EB * HEADS) {
            const int ee = t >> 2, hh = t & 3;
            float a = sp(sred[ee][2 * hh] + sred[ee][2 * hh + 1]);
            a = sp(a * sbn[0][hh] + sbn[1][hh]);
            atomicAdd(&g_denom[sii[ee] * HEADS + hh], __expf(a));
        }
        // per-thread exp (redundant but bit-identical math), for scatter weights
        float a0 = sp(sred[g][2 * h] + sred[g][2 * h + 1]);
        const float ex0 = __expf(sp(a0 * sbn[0][h] + sbn[1][h]));
        float a8 = sp(sred[g + 8][2 * h] + sred[g + 8][2 * h + 1]);
        const float ex8 = __expf(sp(a8 * sbn[0][h] + sbn[1][h]));

        // scatter straight from fragments (no smem staging)
#pragma unroll
        for (int nb = 0; nb < 4; nb++) {
            const int c = w * 32 + nb * 8 + tg * 2;
            float* p0 = &g_num[(size_t)i0 * C + c];
            float* p8 = &g_num[(size_t)i8 * C + c];
            asm volatile("red.global.add.v2.f32 [%0], {%1, %2};"
                         :: "l"(p0), "f"(D[nb][0] * ex0), "f"(D[nb][1] * ex0) : "memory");
            asm volatile("red.global.add.v2.f32 [%0], {%1, %2};"
                         :: "l"(p8), "f"(D[nb][2] * ex8), "f"(D[nb][3] * ex8) : "memory");
        }
    }
}

// out[n, q4] = bias + 0.25 * sum_h num[n,h,q4] / denom[n,h]
__global__ void k_final(const float* __restrict__ bias, float* __restrict__ out) {
    int i = blockIdx.x * blockDim.x + threadIdx.x;   // N_NODES*16 quads
    if (i >= N_NODES * 16) return;
    int n = i >> 4, q = i & 15;
    float inv[HEADS];
#pragma unroll
    for (int hh = 0; hh < HEADS; hh++) {
        float dn = g_denom[n * HEADS + hh];
        inv[hh] = (dn > 0.f) ? 0.25f / dn : 0.f;
    }
    float4 acc = make_float4(0.f, 0.f, 0.f, 0.f);
#pragma unroll
    for (int hh = 0; hh < HEADS; hh++) {
        float4 v = *(const float4*)&g_num[n * C + hh * DIM + q * 4];
        acc.x += v.x * inv[hh]; acc.y += v.y * inv[hh];
        acc.z += v.z * inv[hh]; acc.w += v.w * inv[hh];
    }
    float4 b = *(const float4*)&bias[q * 4];
    acc.x += b.x; acc.y += b.y; acc.z += b.z; acc.w += b.w;
    *(float4*)&out[n * DIM + q * 4] = acc;
}

extern "C" void kernel_launch(void* const* d_in, const int* in_sizes, int n_in,
                              void* d_out, int out_size) {
    const float* x         = (const float*)d_in[0];
    const float* edge_attr = (const float*)d_in[1];
    const float* W         = (const float*)d_in[2];
    const float* att       = (const float*)d_in[3];
    const float* bias      = (const float*)d_in[4];
    const float* bn_g      = (const float*)d_in[5];
    const float* bn_b      = (const float*)d_in[6];
    const float* bn_m      = (const float*)d_in[7];
    const float* bn_v      = (const float*)d_in[8];
    const int*   ei        = (const int*)d_in[9];
    float* out = (float*)d_out;

    k_initA<<<(N_NODES * C + 255) / 256, 256>>>();
    k_initB<<<(N_NODES * HEADS + 255) / 256, 256>>>();
    k_P<<<592, 256>>>(x, W);
    k_edge<<<1184, 256>>>(edge_attr, W, att, bn_g, bn_b, bn_m, bn_v, ei);   // position 4
    k_final<<<(N_NODES * 16 + 255) / 256, 256>>>(bias, out);
}

// round 8
// speedup vs baseline: 2.2585x; 1.0881x over previous
#include <cuda_runtime.h>
#include <math.h>

#define N_NODES 25000
#define N_EDGES 250000
#define DIM 64
#define HEADS 4
#define C 256            // HEADS*DIM
#define EB 16            // edges per tile (mma m16)

// Scratch
__device__ float g_P[N_NODES * C];                       // x @ W_top (fp32 exact)
__device__ __align__(16) float g_num[N_NODES * C];       // unnormalized aggregation
__device__ float g_denom[N_NODES * HEADS];

// exact-enough softplus, 5 instructions, valid for |x| < ~80 (our range: |x|<~10)
__device__ __forceinline__ float sp5(float x) {
    float t, r;
    asm("ex2.approx.f32 %0, %1;" : "=f"(t) : "f"(x * 1.4426950408889634f));
    asm("lg2.approx.f32 %0, %1;" : "=f"(r) : "f"(1.f + t));
    return r * 0.6931471805599453f;
}
__device__ __forceinline__ float spx(float x) {   // exact softplus for k_P path precision
    return fmaxf(x, 0.f) + __logf(1.f + __expf(-fabsf(x)));
}
__device__ __forceinline__ unsigned tf32(float x) {
    float r;
    asm("cvt.rna.tf32.f32 %0, %1;" : "=f"(r) : "f"(x));
    return __float_as_uint(r);
}
__device__ __forceinline__ void mma_tf32(float* d, const unsigned* a, const unsigned* b) {
    asm("mma.sync.aligned.m16n8k8.row.col.f32.tf32.tf32.f32 "
        "{%0,%1,%2,%3}, {%4,%5,%6,%7}, {%8,%9}, {%0,%1,%2,%3};"
        : "+f"(d[0]), "+f"(d[1]), "+f"(d[2]), "+f"(d[3])
        : "r"(a[0]), "r"(a[1]), "r"(a[2]), "r"(a[3]), "r"(b[0]), "r"(b[1]));
}
__device__ __forceinline__ unsigned long long pk2(float a, float b) {
    unsigned long long r;
    asm("mov.b64 %0, {%1, %2};" : "=l"(r) : "f"(a), "f"(b));
    return r;
}
__device__ __forceinline__ void ffma2(unsigned long long& acc,
                                      unsigned long long a, unsigned long long b) {
    asm("fma.rn.f32x2 %0, %1, %2, %0;" : "+l"(acc) : "l"(a), "l"(b));
}
__device__ __forceinline__ float2 unpk2(unsigned long long v) {
    float2 f;
    asm("mov.b64 {%0, %1}, %2;" : "=f"(f.x), "=f"(f.y) : "l"(v));
    return f;
}

__global__ void k_initA() {
    int i = blockIdx.x * blockDim.x + threadIdx.x;
    if (i < N_NODES * C) g_num[i] = 0.f;
}
__global__ void k_initB() {
    int i = blockIdx.x * blockDim.x + threadIdx.x;
    if (i < N_NODES * HEADS) g_denom[i] = 0.f;
}

// P[n, t] = sum_k x[n,k] * W[k, t]  (exact fp32)
__global__ void __launch_bounds__(256, 2) k_P(const float* __restrict__ x,
                                              const float* __restrict__ W) {
    int t = threadIdx.x;
    unsigned long long w2[DIM / 2];
#pragma unroll
    for (int k = 0; k < DIM / 2; k++) w2[k] = pk2(W[(2 * k) * C + t], W[(2 * k + 1) * C + t]);
    __shared__ float4 sx[DIM / 4];
    for (int n = blockIdx.x; n < N_NODES; n += gridDim.x) {
        __syncthreads();
        if (t < 16) sx[t] = ((const float4*)(x + n * DIM))[t];
        __syncthreads();
        unsigned long long a0 = 0ull, a1 = 0ull, a2 = 0ull, a3 = 0ull;
#pragma unroll
        for (int k4 = 0; k4 < 16; k4 += 2) {
            float4 e0 = sx[k4], e1 = sx[k4 + 1];
            ffma2(a0, pk2(e0.x, e0.y), w2[2 * k4]);
            ffma2(a1, pk2(e0.z, e0.w), w2[2 * k4 + 1]);
            ffma2(a2, pk2(e1.x, e1.y), w2[2 * k4 + 2]);
            ffma2(a3, pk2(e1.z, e1.w), w2[2 * k4 + 3]);
        }
        float2 f0 = unpk2(a0), f1 = unpk2(a1), f2 = unpk2(a2), f3 = unpk2(a3);
        g_P[n * C + t] = ((f0.x + f0.y) + (f1.x + f1.y)) + ((f2.x + f2.y) + (f3.x + f3.y));
    }
}

// Fused edge pass, tensor-core matvec, software-pipelined (1 barrier/tile).
__global__ void __launch_bounds__(256, 2) k_edge(
    const float* __restrict__ edge_attr, const float* __restrict__ W,
    const float* __restrict__ att, const float* __restrict__ bn_g,
    const float* __restrict__ bn_b, const float* __restrict__ bn_m,
    const float* __restrict__ bn_v, const int* __restrict__ ei) {
    const int t = threadIdx.x;
    const int w = t >> 5, lane = t & 31;
    const int g = lane >> 2, tg = lane & 3;
    const int h = w >> 1;

    // B fragments (tf32 weights), resident: [nb][ks][2]
    unsigned bf[4][8][2];
#pragma unroll
    for (int nb = 0; nb < 4; nb++) {
        const int n = w * 32 + nb * 8 + g;
#pragma unroll
        for (int ks = 0; ks < 8; ks++) {
            const int k0 = ks * 8 + tg;
            bf[nb][ks][0] = tf32(W[(DIM + k0) * C + n]);
            bf[nb][ks][1] = tf32(W[(DIM + k0 + 4) * C + n]);
        }
    }

    __shared__ unsigned sea[2][EB][68];   // tf32 bits, padded stride -> conflict-free frag loads
    __shared__ int      sii[2][EB], sjj[2][EB];
    __shared__ float    sred[2][EB][8];
    __shared__ float    sbn[2][HEADS];

    if (t < HEADS) {
        float s = bn_g[t] * rsqrtf(bn_v[t] + 1e-5f);
        sbn[0][t] = s;
        sbn[1][t] = bn_b[t] - bn_m[t] * s;
    }

    const int* idx_i = ei;
    const int* idx_j = ei + N_EDGES;
    const int e_ld = t >> 4, q4_ld = t & 15;
    const int stride = gridDim.x * EB;

    // prologue: load tile 0 into buffer 0
    int base0 = blockIdx.x * EB;
    {
        const float4 v = *(const float4*)&edge_attr[(size_t)(base0 + e_ld) * DIM + q4_ld * 4];
        uint4 u = make_uint4(tf32(v.x), tf32(v.y), tf32(v.z), tf32(v.w));
        *(uint4*)&sea[0][e_ld][q4_ld * 4] = u;
        if (t < EB) sii[0][t] = idx_i[base0 + t];
        else if (t < 2 * EB) sjj[0][t - EB] = idx_j[base0 + t - EB];
    }
    __syncthreads();

    int cur = 0;
    for (int base = base0; base < N_EDGES; base += stride) {
        // start next tile's global loads (latency overlapped with compute)
        const int nbase = base + stride;
        const bool has = nbase < N_EDGES;
        float4 vnext;
        int ij_next = 0;
        if (has) {
            vnext = *(const float4*)&edge_attr[(size_t)(nbase + e_ld) * DIM + q4_ld * 4];
            if (t < EB) ij_next = idx_i[nbase + t];
            else if (t < 2 * EB) ij_next = idx_j[nbase + t - EB];
        }
        // pre-read node index for the post-sync denom atomic (avoids buffer hazard)
        const int dnode = sii[cur][(t >> 2) & 15];

        const int i0 = sii[cur][g], i8 = sii[cur][g + 8];
        const int j0 = sjj[cur][g], j8 = sjj[cur][g + 8];

        // Prefetch P gathers (16 independent LDG.64)
        float2 Pi0[4], Pi8[4], Pj0[4], Pj8[4];
#pragma unroll
        for (int nb = 0; nb < 4; nb++) {
            const int c = w * 32 + nb * 8 + tg * 2;
            Pi0[nb] = *(const float2*)&g_P[i0 * C + c];
            Pi8[nb] = *(const float2*)&g_P[i8 * C + c];
            Pj0[nb] = *(const float2*)&g_P[j0 * C + c];
            Pj8[nb] = *(const float2*)&g_P[j8 * C + c];
        }

        // MMA: q[16, 32] for this warp (A fragments are pre-converted bits)
        float D[4][4];
#pragma unroll
        for (int nb = 0; nb < 4; nb++)
#pragma unroll
            for (int r = 0; r < 4; r++) D[nb][r] = 0.f;
#pragma unroll
        for (int ks = 0; ks < 8; ks++) {
            unsigned a[4];
            a[0] = sea[cur][g][ks * 8 + tg];
            a[1] = sea[cur][g + 8][ks * 8 + tg];
            a[2] = sea[cur][g][ks * 8 + tg + 4];
            a[3] = sea[cur][g + 8][ks * 8 + tg + 4];
#pragma unroll
            for (int nb = 0; nb < 4; nb++)
                mma_tf32(D[nb], a, bf[nb][ks]);
        }

        // softplus + logit partials; D overwritten in-place with oj
        float part0 = 0.f, part8 = 0.f;
#pragma unroll
        for (int nb = 0; nb < 4; nb++) {
            const int c = w * 32 + nb * 8 + tg * 2;
            const int d0 = c & 63;
            const float ai0 = att[h * 128 + d0],      ai1 = att[h * 128 + d0 + 1];
            const float aj0 = att[h * 128 + 64 + d0], aj1 = att[h * 128 + 64 + d0 + 1];
            float q, oi;
            q = D[nb][0]; oi = sp5(Pi0[nb].x + q); D[nb][0] = sp5(Pj0[nb].x + q);
            part0 = fmaf(oi, ai0, fmaf(D[nb][0], aj0, part0));
            q = D[nb][1]; oi = sp5(Pi0[nb].y + q); D[nb][1] = sp5(Pj0[nb].y + q);
            part0 = fmaf(oi, ai1, fmaf(D[nb][1], aj1, part0));
            q = D[nb][2]; oi = sp5(Pi8[nb].x + q); D[nb][2] = sp5(Pj8[nb].x + q);
            part8 = fmaf(oi, ai0, fmaf(D[nb][2], aj0, part8));
            q = D[nb][3]; oi = sp5(Pi8[nb].y + q); D[nb][3] = sp5(Pj8[nb].y + q);
            part8 = fmaf(oi, ai1, fmaf(D[nb][3], aj1, part8));
        }
        part0 += __shfl_xor_sync(0xffffffffu, part0, 1);
        part0 += __shfl_xor_sync(0xffffffffu, part0, 2);
        part8 += __shfl_xor_sync(0xffffffffu, part8, 1);
        part8 += __shfl_xor_sync(0xffffffffu, part8, 2);
        if (tg == 0) { sred[cur][g][w] = part0; sred[cur][g + 8][w] = part8; }

        // commit next tile into the other buffer
        if (has) {
            uint4 u = make_uint4(tf32(vnext.x), tf32(vnext.y), tf32(vnext.z), tf32(vnext.w));
            *(uint4*)&sea[cur ^ 1][e_ld][q4_ld * 4] = u;
            if (t < EB) sii[cur ^ 1][t] = ij_next;
            else if (t < 2 * EB) sjj[cur ^ 1][t - EB] = ij_next;
        }
        __syncthreads();   // single barrier: covers sred + next-tile buffers

        // denom atomics (one thread per (edge, head))
        if (t < EB * HEADS) {
            const int ee = t >> 2, hh = t & 3;
            float a = sp5(sred[cur][ee][2 * hh] + sred[cur][ee][2 * hh + 1]);
            a = sp5(a * sbn[0][hh] + sbn[1][hh]);
            atomicAdd(&g_denom[dnode * HEADS + hh], __expf(a));
        }
        // per-thread exp (bit-identical recompute) for scatter weights
        float a0 = sp5(sred[cur][g][2 * h] + sred[cur][g][2 * h + 1]);
        const float ex0 = __expf(sp5(a0 * sbn[0][h] + sbn[1][h]));
        float a8 = sp5(sred[cur][g + 8][2 * h] + sred[cur][g + 8][2 * h + 1]);
        const float ex8 = __expf(sp5(a8 * sbn[0][h] + sbn[1][h]));

        // scatter straight from fragments
#pragma unroll
        for (int nb = 0; nb < 4; nb++) {
            const int c = w * 32 + nb * 8 + tg * 2;
            float* p0 = &g_num[(size_t)i0 * C + c];
            float* p8 = &g_num[(size_t)i8 * C + c];
            asm volatile("red.global.add.v2.f32 [%0], {%1, %2};"
                         :: "l"(p0), "f"(D[nb][0] * ex0), "f"(D[nb][1] * ex0) : "memory");
            asm volatile("red.global.add.v2.f32 [%0], {%1, %2};"
                         :: "l"(p8), "f"(D[nb][2] * ex8), "f"(D[nb][3] * ex8) : "memory");
        }
        cur ^= 1;
    }
}

// out[n, q4] = bias + 0.25 * sum_h num[n,h,q4] / denom[n,h]
__global__ void k_final(const float* __restrict__ bias, float* __restrict__ out) {
    int i = blockIdx.x * blockDim.x + threadIdx.x;   // N_NODES*16 quads
    if (i >= N_NODES * 16) return;
    int n = i >> 4, q = i & 15;
    float inv[HEADS];
#pragma unroll
    for (int hh = 0; hh < HEADS; hh++) {
        float dn = g_denom[n * HEADS + hh];
        inv[hh] = (dn > 0.f) ? 0.25f / dn : 0.f;
    }
    float4 acc = make_float4(0.f, 0.f, 0.f, 0.f);
#pragma unroll
    for (int hh = 0; hh < HEADS; hh++) {
        float4 v = *(const float4*)&g_num[n * C + hh * DIM + q * 4];
        acc.x += v.x * inv[hh]; acc.y += v.y * inv[hh];
        acc.z += v.z * inv[hh]; acc.w += v.w * inv[hh];
    }
    float4 b = *(const float4*)&bias[q * 4];
    acc.x += b.x; acc.y += b.y; acc.z += b.z; acc.w += b.w;
    *(float4*)&out[n * DIM + q * 4] = acc;
}

extern "C" void kernel_launch(void* const* d_in, const int* in_sizes, int n_in,
                              void* d_out, int out_size) {
    const float* x         = (const float*)d_in[0];
    const float* edge_attr = (const float*)d_in[1];
    const float* W         = (const float*)d_in[2];
    const float* att       = (const float*)d_in[3];
    const float* bias      = (const float*)d_in[4];
    const float* bn_g      = (const float*)d_in[5];
    const float* bn_b      = (const float*)d_in[6];
    const float* bn_m      = (const float*)d_in[7];
    const float* bn_v      = (const float*)d_in[8];
    const int*   ei        = (const int*)d_in[9];
    float* out = (float*)d_out;

    k_initA<<<(N_NODES * C + 255) / 256, 256>>>();
    k_initB<<<(N_NODES * HEADS + 255) / 256, 256>>>();
    k_P<<<592, 256>>>(x, W);
    k_edge<<<1184, 256>>>(edge_attr, W, att, bn_g, bn_b, bn_m, bn_v, ei);   // position 4
    k_final<<<(N_NODES * 16 + 255) / 256, 256>>>(bias, out);
}

// round 10
// speedup vs baseline: 2.4172x; 1.0703x over previous
#include <cuda_runtime.h>
#include <math.h>

#define N_NODES 25000
#define N_EDGES 250000
#define DIM 64
#define HEADS 4
#define C 256            // HEADS*DIM
#define EB 16            // edges per tile (mma m16)

// dynamic smem partition (bytes)
#define SB_BYTES   65536                         // 8192 x uint2 (B fragments, tf32 bits)
#define SEA_OFF    SB_BYTES                      // [2][EB][68] unsigned = 8704
#define SII_OFF    (SEA_OFF + 8704)              // [2][EB] int = 128
#define SJJ_OFF    (SII_OFF + 128)               // [2][EB] int = 128
#define SRED_OFF   (SJJ_OFF + 128)               // [2][EB][8] float = 1024
#define SBN_OFF    (SRED_OFF + 1024)             // [2][HEADS] float = 32
#define SMEM_TOTAL (SBN_OFF + 32)

// Scratch
__device__ float g_P[N_NODES * C];                       // x @ W_top (fp32 exact)
__device__ __align__(16) float g_num[N_NODES * C];       // unnormalized aggregation
__device__ float g_denom[N_NODES * HEADS];

// 5-instruction softplus, valid for |x| < ~80 (our range: |x|<~10)
__device__ __forceinline__ float sp5(float x) {
    float t, r;
    asm("ex2.approx.f32 %0, %1;" : "=f"(t) : "f"(x * 1.4426950408889634f));
    asm("lg2.approx.f32 %0, %1;" : "=f"(r) : "f"(1.f + t));
    return r * 0.6931471805599453f;
}
__device__ __forceinline__ unsigned tf32(float x) {
    float r;
    asm("cvt.rna.tf32.f32 %0, %1;" : "=f"(r) : "f"(x));
    return __float_as_uint(r);
}
__device__ __forceinline__ void mma_tf32(float* d, const unsigned* a, unsigned b0, unsigned b1) {
    asm("mma.sync.aligned.m16n8k8.row.col.f32.tf32.tf32.f32 "
        "{%0,%1,%2,%3}, {%4,%5,%6,%7}, {%8,%9}, {%0,%1,%2,%3};"
        : "+f"(d[0]), "+f"(d[1]), "+f"(d[2]), "+f"(d[3])
        : "r"(a[0]), "r"(a[1]), "r"(a[2]), "r"(a[3]), "r"(b0), "r"(b1));
}
__device__ __forceinline__ unsigned long long pk2(float a, float b) {
    unsigned long long r;
    asm("mov.b64 %0, {%1, %2};" : "=l"(r) : "f"(a), "f"(b));
    return r;
}
__device__ __forceinline__ void ffma2(unsigned long long& acc,
                                      unsigned long long a, unsigned long long b) {
    asm("fma.rn.f32x2 %0, %1, %2, %0;" : "+l"(acc) : "l"(a), "l"(b));
}
__device__ __forceinline__ float2 unpk2(unsigned long long v) {
    float2 f;
    asm("mov.b64 {%0, %1}, %2;" : "=f"(f.x), "=f"(f.y) : "l"(v));
    return f;
}

__global__ void k_initA() {   // float4 zero-fill of g_num
    int i = blockIdx.x * blockDim.x + threadIdx.x;
    if (i < N_NODES * C / 4) ((float4*)g_num)[i] = make_float4(0.f, 0.f, 0.f, 0.f);
}
__global__ void k_initB() {
    int i = blockIdx.x * blockDim.x + threadIdx.x;
    if (i < N_NODES * HEADS) g_denom[i] = 0.f;
}

// P[n, t] = sum_k x[n,k] * W[k, t]  (exact fp32)
__global__ void __launch_bounds__(256, 2) k_P(const float* __restrict__ x,
                                              const float* __restrict__ W) {
    int t = threadIdx.x;
    unsigned long long w2[DIM / 2];
#pragma unroll
    for (int k = 0; k < DIM / 2; k++) w2[k] = pk2(W[(2 * k) * C + t], W[(2 * k + 1) * C + t]);
    __shared__ float4 sx[DIM / 4];
    for (int n = blockIdx.x; n < N_NODES; n += gridDim.x) {
        __syncthreads();
        if (t < 16) sx[t] = ((const float4*)(x + n * DIM))[t];
        __syncthreads();
        unsigned long long a0 = 0ull, a1 = 0ull, a2 = 0ull, a3 = 0ull;
#pragma unroll
        for (int k4 = 0; k4 < 16; k4 += 2) {
            float4 e0 = sx[k4], e1 = sx[k4 + 1];
            ffma2(a0, pk2(e0.x, e0.y), w2[2 * k4]);
            ffma2(a1, pk2(e0.z, e0.w), w2[2 * k4 + 1]);
            ffma2(a2, pk2(e1.x, e1.y), w2[2 * k4 + 2]);
            ffma2(a3, pk2(e1.z, e1.w), w2[2 * k4 + 3]);
        }
        float2 f0 = unpk2(a0), f1 = unpk2(a1), f2 = unpk2(a2), f3 = unpk2(a3);
        g_P[n * C + t] = ((f0.x + f0.y) + (f1.x + f1.y)) + ((f2.x + f2.y) + (f3.x + f3.y));
    }
}

// Fused edge pass: tensor-core matvec, B-frags in smem (lane-ordered), pipelined.
__global__ void __launch_bounds__(256, 3) k_edge(
    const float* __restrict__ edge_attr, const float* __restrict__ W,
    const float* __restrict__ att, const float* __restrict__ bn_g,
    const float* __restrict__ bn_b, const float* __restrict__ bn_m,
    const float* __restrict__ bn_v, const int* __restrict__ ei) {
    const int t = threadIdx.x;
    const int w = t >> 5, lane = t & 31;
    const int g = lane >> 2, tg = lane & 3;
    const int h = w >> 1;

    extern __shared__ __align__(16) char dyn[];
    uint2*    sB   = (uint2*)dyn;                                   // [8192] lane-ordered
    unsigned (*sea)[EB][68] = (unsigned(*)[EB][68])(dyn + SEA_OFF); // tf32 bits, padded
    int      (*sii)[EB]     = (int(*)[EB])(dyn + SII_OFF);
    int      (*sjj)[EB]     = (int(*)[EB])(dyn + SJJ_OFF);
    float    (*sred)[EB][8] = (float(*)[EB][8])(dyn + SRED_OFF);
    float    (*sbn)[HEADS]  = (float(*)[HEADS])(dyn + SBN_OFF);

    // Fill B fragments: sB[chunk*32 + lane], chunk = w2*32 + nb*8 + ks
#pragma unroll
    for (int it = 0; it < 32; it++) {
        const int idx = t + it * 256;
        const int chunk = idx >> 5, l = idx & 31;
        const int w2 = chunk >> 5, nb = (chunk >> 3) & 3, ks = chunk & 7;
        const int gg = l >> 2, tt = l & 3;
        const int n  = w2 * 32 + nb * 8 + gg;
        const int k0 = ks * 8 + tt;
        sB[idx] = make_uint2(tf32(W[(DIM + k0) * C + n]), tf32(W[(DIM + k0 + 4) * C + n]));
    }
    if (t < HEADS) {
        float s = bn_g[t] * rsqrtf(bn_v[t] + 1e-5f);
        sbn[0][t] = s;
        sbn[1][t] = bn_b[t] - bn_m[t] * s;
    }

    const int* idx_i = ei;
    const int* idx_j = ei + N_EDGES;
    const int e_ld = t >> 4, q4_ld = t & 15;
    const int stride = gridDim.x * EB;

    // prologue: tile 0 -> buffer 0
    int base0 = blockIdx.x * EB;
    {
        const float4 v = *(const float4*)&edge_attr[(size_t)(base0 + e_ld) * DIM + q4_ld * 4];
        uint4 u = make_uint4(tf32(v.x), tf32(v.y), tf32(v.z), tf32(v.w));
        *(uint4*)&sea[0][e_ld][q4_ld * 4] = u;
        if (t < EB) sii[0][t] = idx_i[base0 + t];
        else if (t < 2 * EB) sjj[0][t - EB] = idx_j[base0 + t - EB];
    }
    __syncthreads();   // covers B-fill + tile 0

    int cur = 0;
    for (int base = base0; base < N_EDGES; base += stride) {
        const int nbase = base + stride;
        const bool has = nbase < N_EDGES;
        float4 vnext;
        int ij_next = 0;
        if (has) {
            vnext = *(const float4*)&edge_attr[(size_t)(nbase + e_ld) * DIM + q4_ld * 4];
            if (t < EB) ij_next = idx_i[nbase + t];
            else if (t < 2 * EB) ij_next = idx_j[nbase + t - EB];
        }
        const int dnode = sii[cur][(t >> 2) & 15];   // pre-read for post-sync denom atomic

        const int i0 = sii[cur][g], i8 = sii[cur][g + 8];
        const int j0 = sjj[cur][g], j8 = sjj[cur][g + 8];

        // Prefetch P gathers (16 independent LDG.64)
        float2 Pi0[4], Pi8[4], Pj0[4], Pj8[4];
#pragma unroll
        for (int nb = 0; nb < 4; nb++) {
            const int c = w * 32 + nb * 8 + tg * 2;
            Pi0[nb] = *(const float2*)&g_P[i0 * C + c];
            Pi8[nb] = *(const float2*)&g_P[i8 * C + c];
            Pj0[nb] = *(const float2*)&g_P[j0 * C + c];
            Pj8[nb] = *(const float2*)&g_P[j8 * C + c];
        }

        // MMA: q[16, 32] for this warp; B operands via conflict-free LDS.64
        float D[4][4];
#pragma unroll
        for (int nb = 0; nb < 4; nb++)
#pragma unroll
            for (int r = 0; r < 4; r++) D[nb][r] = 0.f;
#pragma unroll
        for (int ks = 0; ks < 8; ks++) {
            unsigned a[4];
            a[0] = sea[cur][g][ks * 8 + tg];
            a[1] = sea[cur][g + 8][ks * 8 + tg];
            a[2] = sea[cur][g][ks * 8 + tg + 4];
            a[3] = sea[cur][g + 8][ks * 8 + tg + 4];
#pragma unroll
            for (int nb = 0; nb < 4; nb++) {
                const uint2 b = sB[((w * 32 + nb * 8 + ks)) * 32 + lane];
                mma_tf32(D[nb], a, b.x, b.y);
            }
        }

        // softplus + logit partials; D overwritten in-place with oj
        float part0 = 0.f, part8 = 0.f;
#pragma unroll
        for (int nb = 0; nb < 4; nb++) {
            const int c = w * 32 + nb * 8 + tg * 2;
            const int d0 = c & 63;
            const float ai0 = att[h * 128 + d0],      ai1 = att[h * 128 + d0 + 1];
            const float aj0 = att[h * 128 + 64 + d0], aj1 = att[h * 128 + 64 + d0 + 1];
            float q, oi;
            q = D[nb][0]; oi = sp5(Pi0[nb].x + q); D[nb][0] = sp5(Pj0[nb].x + q);
            part0 = fmaf(oi, ai0, fmaf(D[nb][0], aj0, part0));
            q = D[nb][1]; oi = sp5(Pi0[nb].y + q); D[nb][1] = sp5(Pj0[nb].y + q);
            part0 = fmaf(oi, ai1, fmaf(D[nb][1], aj1, part0));
            q = D[nb][2]; oi = sp5(Pi8[nb].x + q); D[nb][2] = sp5(Pj8[nb].x + q);
            part8 = fmaf(oi, ai0, fmaf(D[nb][2], aj0, part8));
            q = D[nb][3]; oi = sp5(Pi8[nb].y + q); D[nb][3] = sp5(Pj8[nb].y + q);
            part8 = fmaf(oi, ai1, fmaf(D[nb][3], aj1, part8));
        }
        part0 += __shfl_xor_sync(0xffffffffu, part0, 1);
        part0 += __shfl_xor_sync(0xffffffffu, part0, 2);
        part8 += __shfl_xor_sync(0xffffffffu, part8, 1);
        part8 += __shfl_xor_sync(0xffffffffu, part8, 2);
        if (tg == 0) { sred[cur][g][w] = part0; sred[cur][g + 8][w] = part8; }

        // commit next tile into the other buffer
        if (has) {
            uint4 u = make_uint4(tf32(vnext.x), tf32(vnext.y), tf32(vnext.z), tf32(vnext.w));
            *(uint4*)&sea[cur ^ 1][e_ld][q4_ld * 4] = u;
            if (t < EB) sii[cur ^ 1][t] = ij_next;
            else if (t < 2 * EB) sjj[cur ^ 1][t - EB] = ij_next;
        }
        __syncthreads();   // single barrier per tile

        // denom atomics (one thread per (edge, head))
        if (t < EB * HEADS) {
            const int ee = t >> 2, hh = t & 3;
            float a = sp5(sred[cur][ee][2 * hh] + sred[cur][ee][2 * hh + 1]);
            a = sp5(a * sbn[0][hh] + sbn[1][hh]);
            atomicAdd(&g_denom[dnode * HEADS + hh], __expf(a));
        }
        // per-thread exp (bit-identical recompute) for scatter weights
        float a0 = sp5(sred[cur][g][2 * h] + sred[cur][g][2 * h + 1]);
        const float ex0 = __expf(sp5(a0 * sbn[0][h] + sbn[1][h]));
        float a8 = sp5(sred[cur][g + 8][2 * h] + sred[cur][g + 8][2 * h + 1]);
        const float ex8 = __expf(sp5(a8 * sbn[0][h] + sbn[1][h]));

        // scatter straight from fragments
#pragma unroll
        for (int nb = 0; nb < 4; nb++) {
            const int c = w * 32 + nb * 8 + tg * 2;
            float* p0 = &g_num[(size_t)i0 * C + c];
            float* p8 = &g_num[(size_t)i8 * C + c];
            asm volatile("red.global.add.v2.f32 [%0], {%1, %2};"
                         :: "l"(p0), "f"(D[nb][0] * ex0), "f"(D[nb][1] * ex0) : "memory");
            asm volatile("red.global.add.v2.f32 [%0], {%1, %2};"
                         :: "l"(p8), "f"(D[nb][2] * ex8), "f"(D[nb][3] * ex8) : "memory");
        }
        cur ^= 1;
    }
}

// out[n, q4] = bias + 0.25 * sum_h num[n,h,q4] / denom[n,h]
__global__ void k_final(const float* __restrict__ bias, float* __restrict__ out) {
    int i = blockIdx.x * blockDim.x + threadIdx.x;   // N_NODES*16 quads
    if (i >= N_NODES * 16) return;
    int n = i >> 4, q = i & 15;
    float inv[HEADS];
#pragma unroll
    for (int hh = 0; hh < HEADS; hh++) {
        float dn = g_denom[n * HEADS + hh];
        inv[hh] = (dn > 0.f) ? 0.25f / dn : 0.f;
    }
    float4 acc = make_float4(0.f, 0.f, 0.f, 0.f);
#pragma unroll
    for (int hh = 0; hh < HEADS; hh++) {
        float4 v = *(const float4*)&g_num[n * C + hh * DIM + q * 4];
        acc.x += v.x * inv[hh]; acc.y += v.y * inv[hh];
        acc.z += v.z * inv[hh]; acc.w += v.w * inv[hh];
    }
    float4 b = *(const float4*)&bias[q * 4];
    acc.x += b.x; acc.y += b.y; acc.z += b.z; acc.w += b.w;
    *(float4*)&out[n * DIM + q * 4] = acc;
}

extern "C" void kernel_launch(void* const* d_in, const int* in_sizes, int n_in,
                              void* d_out, int out_size) {
    const float* x         = (const float*)d_in[0];
    const float* edge_attr = (const float*)d_in[1];
    const float* W         = (const float*)d_in[2];
    const float* att       = (const float*)d_in[3];
    const float* bias      = (const float*)d_in[4];
    const float* bn_g      = (const float*)d_in[5];
    const float* bn_b      = (const float*)d_in[6];
    const float* bn_m      = (const float*)d_in[7];
    const float* bn_v      = (const float*)d_in[8];
    const int*   ei        = (const int*)d_in[9];
    float* out = (float*)d_out;

    cudaFuncSetAttribute(k_edge, cudaFuncAttributeMaxDynamicSharedMemorySize, SMEM_TOTAL);

    k_initA<<<(N_NODES * C / 4 + 255) / 256, 256>>>();
    k_initB<<<(N_NODES * HEADS + 255) / 256, 256>>>();
    k_P<<<592, 256>>>(x, W);
    k_edge<<<444, 256, SMEM_TOTAL>>>(edge_attr, W, att, bn_g, bn_b, bn_m, bn_v, ei);
    k_final<<<(N_NODES * 16 + 255) / 256, 256>>>(bias, out);
}

// round 11
// speedup vs baseline: 2.7063x; 1.1196x over previous
#include <cuda_runtime.h>
#include <math.h>

#define N_NODES 25000
#define N_EDGES 250000
#define DIM 64
#define HEADS 4
#define C 256            // HEADS*DIM
#define EB 16            // edges per tile (mma m16)
#define SQS 264          // sq row stride (floats): conflict-free STS

// dynamic smem partition (bytes)
#define SB_BYTES   32768                          // 8192 x uint (bf16-pair B frags)
#define SEA_OFF    SB_BYTES                       // [2][EB][68] unsigned = 8704
#define SQ_OFF     (SEA_OFF + 8704)               // [2][EB][SQS] float = 33792
#define SII_OFF    (SQ_OFF + 33792)               // [2][EB] int = 128
#define SJJ_OFF    (SII_OFF + 128)                // [2][EB] int = 128
#define SBN_OFF    (SJJ_OFF + 128)                // [2][HEADS] float = 32
#define SMEM_TOTAL (SBN_OFF + 32)

// Scratch
__device__ float g_P[N_NODES * C];                       // x @ W_top (fp32 exact)
__device__ __align__(16) float g_num[N_NODES * C];       // unnormalized aggregation
__device__ float g_denom[N_NODES * HEADS];

// 5-instruction softplus, valid for |x| < ~80 (our range: |x|<~10)
__device__ __forceinline__ float sp5(float x) {
    float t, r;
    asm("ex2.approx.f32 %0, %1;" : "=f"(t) : "f"(x * 1.4426950408889634f));
    asm("lg2.approx.f32 %0, %1;" : "=f"(r) : "f"(1.f + t));
    return r * 0.6931471805599453f;
}
__device__ __forceinline__ unsigned tf32(float x) {
    float r;
    asm("cvt.rna.tf32.f32 %0, %1;" : "=f"(r) : "f"(x));
    return __float_as_uint(r);
}
// pack bf16(a) in high half, bf16(b) in low half
__device__ __forceinline__ unsigned pk_bf16(float a, float b) {
    unsigned r;
    asm("{.reg .b16 lo, hi; cvt.rn.bf16.f32 hi, %1; cvt.rn.bf16.f32 lo, %2; mov.b32 %0, {lo, hi};}"
        : "=r"(r) : "f"(a), "f"(b));
    return r;
}
__device__ __forceinline__ void mma_tf32(float* d, const unsigned* a, unsigned b0, unsigned b1) {
    asm("mma.sync.aligned.m16n8k8.row.col.f32.tf32.tf32.f32 "
        "{%0,%1,%2,%3}, {%4,%5,%6,%7}, {%8,%9}, {%0,%1,%2,%3};"
        : "+f"(d[0]), "+f"(d[1]), "+f"(d[2]), "+f"(d[3])
        : "r"(a[0]), "r"(a[1]), "r"(a[2]), "r"(a[3]), "r"(b0), "r"(b1));
}
__device__ __forceinline__ unsigned long long pk2(float a, float b) {
    unsigned long long r;
    asm("mov.b64 %0, {%1, %2};" : "=l"(r) : "f"(a), "f"(b));
    return r;
}
__device__ __forceinline__ void ffma2(unsigned long long& acc,
                                      unsigned long long a, unsigned long long b) {
    asm("fma.rn.f32x2 %0, %1, %2, %0;" : "+l"(acc) : "l"(a), "l"(b));
}
__device__ __forceinline__ float2 unpk2(unsigned long long v) {
    float2 f;
    asm("mov.b64 {%0, %1}, %2;" : "=f"(f.x), "=f"(f.y) : "l"(v));
    return f;
}
__device__ __forceinline__ float4 sp4(float4 p, float4 q) {
    return make_float4(sp5(p.x + q.x), sp5(p.y + q.y), sp5(p.z + q.z), sp5(p.w + q.w));
}
__device__ __forceinline__ float dot4acc(float acc, float4 o, float4 c) {
    return fmaf(o.x, c.x, fmaf(o.y, c.y, fmaf(o.z, c.z, fmaf(o.w, c.w, acc))));
}
__device__ __forceinline__ void red4(float* p, float4 v) {
    asm volatile("red.global.add.v4.f32 [%0], {%1, %2, %3, %4};"
                 :: "l"(p), "f"(v.x), "f"(v.y), "f"(v.z), "f"(v.w) : "memory");
}

__global__ void k_initA() {
    int i = blockIdx.x * blockDim.x + threadIdx.x;
    if (i < N_NODES * C / 4) ((float4*)g_num)[i] = make_float4(0.f, 0.f, 0.f, 0.f);
}
__global__ void k_initB() {
    int i = blockIdx.x * blockDim.x + threadIdx.x;
    if (i < N_NODES * HEADS) g_denom[i] = 0.f;
}

// P[n, t] = sum_k x[n,k] * W[k, t]  (exact fp32)
__global__ void __launch_bounds__(256, 2) k_P(const float* __restrict__ x,
                                              const float* __restrict__ W) {
    int t = threadIdx.x;
    unsigned long long w2[DIM / 2];
#pragma unroll
    for (int k = 0; k < DIM / 2; k++) w2[k] = pk2(W[(2 * k) * C + t], W[(2 * k + 1) * C + t]);
    __shared__ float4 sx[DIM / 4];
    for (int n = blockIdx.x; n < N_NODES; n += gridDim.x) {
        __syncthreads();
        if (t < 16) sx[t] = ((const float4*)(x + n * DIM))[t];
        __syncthreads();
        unsigned long long a0 = 0ull, a1 = 0ull, a2 = 0ull, a3 = 0ull;
#pragma unroll
        for (int k4 = 0; k4 < 16; k4 += 2) {
            float4 e0 = sx[k4], e1 = sx[k4 + 1];
            ffma2(a0, pk2(e0.x, e0.y), w2[2 * k4]);
            ffma2(a1, pk2(e0.z, e0.w), w2[2 * k4 + 1]);
            ffma2(a2, pk2(e1.x, e1.y), w2[2 * k4 + 2]);
            ffma2(a3, pk2(e1.z, e1.w), w2[2 * k4 + 3]);
        }
        float2 f0 = unpk2(a0), f1 = unpk2(a1), f2 = unpk2(a2), f3 = unpk2(a3);
        g_P[n * C + t] = ((f0.x + f0.y) + (f1.x + f1.y)) + ((f2.x + f2.y) + (f3.x + f3.y));
    }
}

// Fused edge pass: MMA (fragment layout) -> smem redistribute -> coalesced epilogue.
__global__ void __launch_bounds__(256, 3) k_edge(
    const float* __restrict__ edge_attr, const float* __restrict__ W,
    const float* __restrict__ att, const float* __restrict__ bn_g,
    const float* __restrict__ bn_b, const float* __restrict__ bn_m,
    const float* __restrict__ bn_v, const int* __restrict__ ei) {
    const int t = threadIdx.x;
    const int w = t >> 5, lane = t & 31;
    const int g = lane >> 2, tg = lane & 3;

    extern __shared__ __align__(16) char dyn[];
    unsigned* sBh = (unsigned*)dyn;                                  // [8192] bf16-pair
    unsigned (*sea)[EB][68]  = (unsigned(*)[EB][68])(dyn + SEA_OFF); // tf32 bits
    float    (*sq)[EB][SQS]  = (float(*)[EB][SQS])(dyn + SQ_OFF);
    int      (*sii)[EB]      = (int(*)[EB])(dyn + SII_OFF);
    int      (*sjj)[EB]      = (int(*)[EB])(dyn + SJJ_OFF);
    float    (*sbn)[HEADS]   = (float(*)[HEADS])(dyn + SBN_OFF);

    // Fill B fragments: sBh[chunk*32 + lane], chunk = wv*32 + nb*8 + ks
#pragma unroll
    for (int it = 0; it < 32; it++) {
        const int idx = t + it * 256;
        const int chunk = idx >> 5, l = idx & 31;
        const int wv = chunk >> 5, nb = (chunk >> 3) & 3, ks = chunk & 7;
        const int gg = l >> 2, tt = l & 3;
        const int n  = wv * 32 + nb * 8 + gg;
        const int k0 = ks * 8 + tt;
        sBh[idx] = pk_bf16(W[(DIM + k0) * C + n], W[(DIM + k0 + 4) * C + n]);
    }
    if (t < HEADS) {
        float s = bn_g[t] * rsqrtf(bn_v[t] + 1e-5f);
        sbn[0][t] = s;
        sbn[1][t] = bn_b[t] - bn_m[t] * s;
    }

    // per-lane att coefficients for the coalesced epilogue
    const int ha = lane >> 4, hb = 2 + ha;          // head of col group a (0..127) / b (128..255)
    const int da = (lane * 4) & 63;
    const float4 aia = *(const float4*)&att[ha * 128 + da];
    const float4 aja = *(const float4*)&att[ha * 128 + 64 + da];
    const float4 aib = *(const float4*)&att[hb * 128 + da];
    const float4 ajb = *(const float4*)&att[hb * 128 + 64 + da];

    const int* idx_i = ei;
    const int* idx_j = ei + N_EDGES;
    const int e_ld = t >> 4, q4_ld = t & 15;
    const int stride = gridDim.x * EB;

    // prologue: tile 0 -> buffer 0
    int base0 = blockIdx.x * EB;
    {
        const float4 v = *(const float4*)&edge_attr[(size_t)(base0 + e_ld) * DIM + q4_ld * 4];
        uint4 u = make_uint4(tf32(v.x), tf32(v.y), tf32(v.z), tf32(v.w));
        *(uint4*)&sea[0][e_ld][q4_ld * 4] = u;
        if (t < EB) sii[0][t] = idx_i[base0 + t];
        else if (t < 2 * EB) sjj[0][t - EB] = idx_j[base0 + t - EB];
    }
    __syncthreads();   // covers B-fill + sbn + tile 0

    const float sa_a = sbn[0][ha], sb_a = sbn[1][ha];
    const float sa_b = sbn[0][hb], sb_b = sbn[1][hb];
    const int e0 = 2 * w, e1 = 2 * w + 1;

    int cur = 0;
    for (int base = base0; base < N_EDGES; base += stride) {
        const int nbase = base + stride;
        const bool has = nbase < N_EDGES;
        float4 vnext;
        int ij_next = 0;
        if (has) {
            vnext = *(const float4*)&edge_attr[(size_t)(nbase + e_ld) * DIM + q4_ld * 4];
            if (t < EB) ij_next = idx_i[nbase + t];
            else if (t < 2 * EB) ij_next = idx_j[nbase + t - EB];
        }
        // pre-read this warp's edge indices (sii[cur] stable until next iteration)
        const int ni0 = sii[cur][e0], nj0 = sjj[cur][e0];
        const int ni1 = sii[cur][e1], nj1 = sjj[cur][e1];

        // ---- MMA: q[16 edges, 32 cols] in fragment layout ----
        float D[4][4];
#pragma unroll
        for (int nb = 0; nb < 4; nb++)
#pragma unroll
            for (int r = 0; r < 4; r++) D[nb][r] = 0.f;
#pragma unroll
        for (int ks = 0; ks < 8; ks++) {
            unsigned a[4];
            a[0] = sea[cur][g][ks * 8 + tg];
            a[1] = sea[cur][g + 8][ks * 8 + tg];
            a[2] = sea[cur][g][ks * 8 + tg + 4];
            a[3] = sea[cur][g + 8][ks * 8 + tg + 4];
#pragma unroll
            for (int nb = 0; nb < 4; nb++) {
                const unsigned u = sBh[(w * 32 + nb * 8 + ks) * 32 + lane];
                mma_tf32(D[nb], a, u & 0xffff0000u, u << 16);
            }
        }

        // ---- redistribute q to edge-major smem (conflict-free STS.64) ----
#pragma unroll
        for (int nb = 0; nb < 4; nb++) {
            const int c = w * 32 + nb * 8 + tg * 2;
            *(float2*)&sq[cur][g][c]     = make_float2(D[nb][0], D[nb][1]);
            *(float2*)&sq[cur][g + 8][c] = make_float2(D[nb][2], D[nb][3]);
        }

        // commit next tile into the other buffer
        if (has) {
            uint4 u = make_uint4(tf32(vnext.x), tf32(vnext.y), tf32(vnext.z), tf32(vnext.w));
            *(uint4*)&sea[cur ^ 1][e_ld][q4_ld * 4] = u;
            if (t < EB) sii[cur ^ 1][t] = ij_next;
            else if (t < 2 * EB) sjj[cur ^ 1][t - EB] = ij_next;
        }
        __syncthreads();   // single barrier per tile

        // ---- coalesced epilogue: warp w owns edges e0, e1 (full 256-col rows) ----
        const int l4 = lane * 4;
#pragma unroll
        for (int sub = 0; sub < 2; sub++) {
            const int e  = sub ? e1 : e0;
            const int ni = sub ? ni1 : ni0;
            const int nj = sub ? nj1 : nj0;

            const float4 qa = *(const float4*)&sq[cur][e][l4];
            const float4 qb = *(const float4*)&sq[cur][e][128 + l4];
            const float4 pia = *(const float4*)&g_P[ni * C + l4];
            const float4 pib = *(const float4*)&g_P[ni * C + 128 + l4];
            const float4 pja = *(const float4*)&g_P[nj * C + l4];
            const float4 pjb = *(const float4*)&g_P[nj * C + 128 + l4];

            const float4 oia = sp4(pia, qa), oja = sp4(pja, qa);
            const float4 oib = sp4(pib, qb), ojb = sp4(pjb, qb);

            float pa = dot4acc(dot4acc(0.f, oia, aia), oja, aja);
            float pb = dot4acc(dot4acc(0.f, oib, aib), ojb, ajb);
#pragma unroll
            for (int off = 1; off < 16; off <<= 1) {
                pa += __shfl_xor_sync(0xffffffffu, pa, off);
                pb += __shfl_xor_sync(0xffffffffu, pb, off);
            }
            // per-16-lane-group: pa = logit sum for head ha, pb for head hb
            const float exa = __expf(sp5(fmaf(sp5(pa), sa_a, sb_a)));
            const float exb = __expf(sp5(fmaf(sp5(pb), sa_b, sb_b)));
            if ((lane & 15) == 0) {
                atomicAdd(&g_denom[ni * HEADS + ha], exa);
                atomicAdd(&g_denom[ni * HEADS + hb], exb);
            }
            red4(&g_num[(size_t)ni * C + l4],
                 make_float4(oja.x * exa, oja.y * exa, oja.z * exa, oja.w * exa));
            red4(&g_num[(size_t)ni * C + 128 + l4],
                 make_float4(ojb.x * exb, ojb.y * exb, ojb.z * exb, ojb.w * exb));
        }
        cur ^= 1;
    }
}

// out[n, q4] = bias + 0.25 * sum_h num[n,h,q4] / denom[n,h]
__global__ void k_final(const float* __restrict__ bias, float* __restrict__ out) {
    int i = blockIdx.x * blockDim.x + threadIdx.x;   // N_NODES*16 quads
    if (i >= N_NODES * 16) return;
    int n = i >> 4, q = i & 15;
    float inv[HEADS];
#pragma unroll
    for (int hh = 0; hh < HEADS; hh++) {
        float dn = g_denom[n * HEADS + hh];
        inv[hh] = (dn > 0.f) ? 0.25f / dn : 0.f;
    }
    float4 acc = make_float4(0.f, 0.f, 0.f, 0.f);
#pragma unroll
    for (int hh = 0; hh < HEADS; hh++) {
        float4 v = *(const float4*)&g_num[n * C + hh * DIM + q * 4];
        acc.x += v.x * inv[hh]; acc.y += v.y * inv[hh];
        acc.z += v.z * inv[hh]; acc.w += v.w * inv[hh];
    }
    float4 b = *(const float4*)&bias[q * 4];
    acc.x += b.x; acc.y += b.y; acc.z += b.z; acc.w += b.w;
    *(float4*)&out[n * DIM + q * 4] = acc;
}

extern "C" void kernel_launch(void* const* d_in, const int* in_sizes, int n_in,
                              void* d_out, int out_size) {
    const float* x         = (const float*)d_in[0];
    const float* edge_attr = (const float*)d_in[1];
    const float* W         = (const float*)d_in[2];
    const float* att       = (const float*)d_in[3];
    const float* bias      = (const float*)d_in[4];
    const float* bn_g      = (const float*)d_in[5];
    const float* bn_b      = (const float*)d_in[6];
    const float* bn_m      = (const float*)d_in[7];
    const float* bn_v      = (const float*)d_in[8];
    const int*   ei        = (const int*)d_in[9];
    float* out = (float*)d_out;

    cudaFuncSetAttribute(k_edge, cudaFuncAttributeMaxDynamicSharedMemorySize, SMEM_TOTAL);

    k_initA<<<(N_NODES * C / 4 + 255) / 256, 256>>>();
    k_initB<<<(N_NODES * HEADS + 255) / 256, 256>>>();
    k_P<<<592, 256>>>(x, W);
    k_edge<<<444, 256, SMEM_TOTAL>>>(edge_attr, W, att, bn_g, bn_b, bn_m, bn_v, ei);
    k_final<<<(N_NODES * 16 + 255) / 256, 256>>>(bias, out);
}